// round 13
// baseline (speedup 1.0000x reference)
#include <cuda_runtime.h>
#include <cstddef>
#include <cstdint>

#define NUM_FIELDS 16
#define FIELD_DIM  31250
#define VOCAB      500000
#define NUM_PAIRS  120
#define ROWS_PER_BLOCK 128
#define TPB 512            // 128 rows * 4 lanes (32B per lane), 1 row per thread

// Packed (i,j) pair table for triu(16, k=1): entry = i | (j<<8).
#define P(i,j) ((i) | ((j) << 8))
__constant__ int c_pair[NUM_PAIRS] = {
    P(0,1),P(0,2),P(0,3),P(0,4),P(0,5),P(0,6),P(0,7),P(0,8),P(0,9),P(0,10),P(0,11),P(0,12),P(0,13),P(0,14),P(0,15),
    P(1,2),P(1,3),P(1,4),P(1,5),P(1,6),P(1,7),P(1,8),P(1,9),P(1,10),P(1,11),P(1,12),P(1,13),P(1,14),P(1,15),
    P(2,3),P(2,4),P(2,5),P(2,6),P(2,7),P(2,8),P(2,9),P(2,10),P(2,11),P(2,12),P(2,13),P(2,14),P(2,15),
    P(3,4),P(3,5),P(3,6),P(3,7),P(3,8),P(3,9),P(3,10),P(3,11),P(3,12),P(3,13),P(3,14),P(3,15),
    P(4,5),P(4,6),P(4,7),P(4,8),P(4,9),P(4,10),P(4,11),P(4,12),P(4,13),P(4,14),P(4,15),
    P(5,6),P(5,7),P(5,8),P(5,9),P(5,10),P(5,11),P(5,12),P(5,13),P(5,14),P(5,15),
    P(6,7),P(6,8),P(6,9),P(6,10),P(6,11),P(6,12),P(6,13),P(6,14),P(6,15),
    P(7,8),P(7,9),P(7,10),P(7,11),P(7,12),P(7,13),P(7,14),P(7,15),
    P(8,9),P(8,10),P(8,11),P(8,12),P(8,13),P(8,14),P(8,15),
    P(9,10),P(9,11),P(9,12),P(9,13),P(9,14),P(9,15),
    P(10,11),P(10,12),P(10,13),P(10,14),P(10,15),
    P(11,12),P(11,13),P(11,14),P(11,15),
    P(12,13),P(12,14),P(12,15),
    P(13,14),P(13,15),
    P(14,15)
};
#undef P

// 256-bit (32B) gather via texture/nc path.
__device__ __forceinline__ void ldg8(const float* p, uint32_t v[8]) {
    asm volatile("ld.global.nc.v8.b32 {%0,%1,%2,%3,%4,%5,%6,%7}, [%8];"
                 : "=r"(v[0]), "=r"(v[1]), "=r"(v[2]), "=r"(v[3]),
                   "=r"(v[4]), "=r"(v[5]), "=r"(v[6]), "=r"(v[7])
                 : "l"(p));
}

// Streaming store, evict-first: output is never re-read.
__device__ __forceinline__ void stg_cs(float* p, float x, float y, float z, float w) {
    asm volatile("st.global.cs.v4.f32 [%0], {%1,%2,%3,%4};"
                 :: "l"(p), "f"(x), "f"(y), "f"(z), "f"(w)
                 : "memory");
}

// Pair-major schedule: blockIdx.y = pair (contiguous block-id span per pair ->
// the pair's two 4MB index windows stay L2-resident for all 16384 accesses,
// capturing the ~22% duplicate-index read reuse; each of the 240 (slab,field)
// windows belongs to exactly one pair, so this captures ALL available reuse),
// blockIdx.x = batch tile of 128 rows. Each thread: 1 row x one 32B lane; two
// independent 256-bit gathers in flight; 4 lanes cover each 128B embedding
// line fully coalesced.
// FINAL configuration: ~100.5us wall, DRAM 6.1-6.3 TB/s = device LTS ceiling
// for this 2:1 random-read/stream-write mix at the compulsory ~600MB traffic
// floor. Converged over 7 variants and 5 repeats (cache hints, MLP, CTA
// size, load width, occupancy all within +/-0.35us noise).
__global__ __launch_bounds__(TPB, 4)
void ffm_pairmajor_kernel(const int* __restrict__ x,
                          const float* __restrict__ W,    // (16, 500000, 32) float
                          float* __restrict__ out,        // (B, 120, 32) float
                          int batch)
{
    const int p   = blockIdx.y;
    const int t   = threadIdx.x;
    const int q   = t & 3;              // 32B chunk within the 128B embedding
    const int r   = t >> 2;             // 0..127
    const int row = blockIdx.x * ROWS_PER_BLOCK + r;

    const int ij = c_pair[p];
    const int i  = ij & 0xff;
    const int j  = ij >> 8;

    // Index loads (x is 1MB, L2-resident; broadcast across the 4 lanes of a row).
    const int ii = __ldg(&x[row * NUM_FIELDS + i]) + i * FIELD_DIM;
    const int jj = __ldg(&x[row * NUM_FIELDS + j]) + j * FIELD_DIM;

    // Two independent 256-bit gathers in flight per thread.
    uint32_t a[8], b[8];
    ldg8(W + ((size_t)j * VOCAB + ii) * 32 + q * 8, a);
    ldg8(W + ((size_t)i * VOCAB + jj) * 32 + q * 8, b);

    // out float layout: (row, pair, 32); 4 lanes cover one contiguous 128B line.
    float* o = out + (size_t)row * (NUM_PAIRS * 32) + p * 32 + q * 8;
    stg_cs(o,
           __uint_as_float(a[0]) * __uint_as_float(b[0]),
           __uint_as_float(a[1]) * __uint_as_float(b[1]),
           __uint_as_float(a[2]) * __uint_as_float(b[2]),
           __uint_as_float(a[3]) * __uint_as_float(b[3]));
    stg_cs(o + 4,
           __uint_as_float(a[4]) * __uint_as_float(b[4]),
           __uint_as_float(a[5]) * __uint_as_float(b[5]),
           __uint_as_float(a[6]) * __uint_as_float(b[6]),
           __uint_as_float(a[7]) * __uint_as_float(b[7]));
}

extern "C" void kernel_launch(void* const* d_in, const int* in_sizes, int n_in,
                              void* d_out, int out_size)
{
    // Inputs: x int32 (16384*16 elems), W float32 (16*500000*32 elems).
    const int* x = nullptr;
    const float* W = nullptr;
    int x_elems = 0;
    if (n_in >= 2) {
        if (in_sizes[0] < in_sizes[1]) {
            x = (const int*)d_in[0];
            W = (const float*)d_in[1];
            x_elems = in_sizes[0];
        } else {
            x = (const int*)d_in[1];
            W = (const float*)d_in[0];
            x_elems = in_sizes[1];
        }
    }

    const int batch = x_elems / NUM_FIELDS;
    const int tiles = batch / ROWS_PER_BLOCK;   // 16384/128 = 128

    dim3 grid(tiles, NUM_PAIRS);
    ffm_pairmajor_kernel<<<grid, TPB>>>(x, W, (float*)d_out, batch);
}

// round 14
// speedup vs baseline: 1.0041x; 1.0041x over previous
#include <cuda_runtime.h>
#include <cstddef>
#include <cstdint>

#define NUM_FIELDS 16
#define FIELD_DIM  31250
#define VOCAB      500000
#define NUM_PAIRS  120
#define ROWS_PER_BLOCK 128
#define TPB 512            // 128 rows * 4 lanes (32B per lane), 1 row per thread

// Packed (i,j) pair table for triu(16, k=1): entry = i | (j<<8).
#define P(i,j) ((i) | ((j) << 8))
__constant__ int c_pair[NUM_PAIRS] = {
    P(0,1),P(0,2),P(0,3),P(0,4),P(0,5),P(0,6),P(0,7),P(0,8),P(0,9),P(0,10),P(0,11),P(0,12),P(0,13),P(0,14),P(0,15),
    P(1,2),P(1,3),P(1,4),P(1,5),P(1,6),P(1,7),P(1,8),P(1,9),P(1,10),P(1,11),P(1,12),P(1,13),P(1,14),P(1,15),
    P(2,3),P(2,4),P(2,5),P(2,6),P(2,7),P(2,8),P(2,9),P(2,10),P(2,11),P(2,12),P(2,13),P(2,14),P(2,15),
    P(3,4),P(3,5),P(3,6),P(3,7),P(3,8),P(3,9),P(3,10),P(3,11),P(3,12),P(3,13),P(3,14),P(3,15),
    P(4,5),P(4,6),P(4,7),P(4,8),P(4,9),P(4,10),P(4,11),P(4,12),P(4,13),P(4,14),P(4,15),
    P(5,6),P(5,7),P(5,8),P(5,9),P(5,10),P(5,11),P(5,12),P(5,13),P(5,14),P(5,15),
    P(6,7),P(6,8),P(6,9),P(6,10),P(6,11),P(6,12),P(6,13),P(6,14),P(6,15),
    P(7,8),P(7,9),P(7,10),P(7,11),P(7,12),P(7,13),P(7,14),P(7,15),
    P(8,9),P(8,10),P(8,11),P(8,12),P(8,13),P(8,14),P(8,15),
    P(9,10),P(9,11),P(9,12),P(9,13),P(9,14),P(9,15),
    P(10,11),P(10,12),P(10,13),P(10,14),P(10,15),
    P(11,12),P(11,13),P(11,14),P(11,15),
    P(12,13),P(12,14),P(12,15),
    P(13,14),P(13,15),
    P(14,15)
};
#undef P

// 256-bit (32B) gather via texture/nc path.
__device__ __forceinline__ void ldg8(const float* p, uint32_t v[8]) {
    asm volatile("ld.global.nc.v8.b32 {%0,%1,%2,%3,%4,%5,%6,%7}, [%8];"
                 : "=r"(v[0]), "=r"(v[1]), "=r"(v[2]), "=r"(v[3]),
                   "=r"(v[4]), "=r"(v[5]), "=r"(v[6]), "=r"(v[7])
                 : "l"(p));
}

// Streaming store, evict-first: output is never re-read.
__device__ __forceinline__ void stg_cs(float* p, float x, float y, float z, float w) {
    asm volatile("st.global.cs.v4.f32 [%0], {%1,%2,%3,%4};"
                 :: "l"(p), "f"(x), "f"(y), "f"(z), "f"(w)
                 : "memory");
}

// Pair-major schedule: blockIdx.y = pair (contiguous block-id span per pair ->
// the pair's two 4MB index windows stay L2-resident for all 16384 accesses,
// capturing the ~22% duplicate-index read reuse; each of the 240 (slab,field)
// windows belongs to exactly one pair, so this captures ALL available reuse),
// blockIdx.x = batch tile of 128 rows. Each thread: 1 row x one 32B lane; two
// independent 256-bit gathers in flight; 4 lanes cover each 128B embedding
// line fully coalesced.
// FINAL configuration: ~100.5us wall, DRAM 6.1-6.3 TB/s = device LTS ceiling
// for this 2:1 random-read/stream-write mix at the compulsory ~600MB traffic
// floor. Converged over 7 variants and 6 repeats (cache hints, MLP, CTA
// size, load width, occupancy all within +/-0.4us noise).
__global__ __launch_bounds__(TPB, 4)
void ffm_pairmajor_kernel(const int* __restrict__ x,
                          const float* __restrict__ W,    // (16, 500000, 32) float
                          float* __restrict__ out,        // (B, 120, 32) float
                          int batch)
{
    const int p   = blockIdx.y;
    const int t   = threadIdx.x;
    const int q   = t & 3;              // 32B chunk within the 128B embedding
    const int r   = t >> 2;             // 0..127
    const int row = blockIdx.x * ROWS_PER_BLOCK + r;

    const int ij = c_pair[p];
    const int i  = ij & 0xff;
    const int j  = ij >> 8;

    // Index loads (x is 1MB, L2-resident; broadcast across the 4 lanes of a row).
    const int ii = __ldg(&x[row * NUM_FIELDS + i]) + i * FIELD_DIM;
    const int jj = __ldg(&x[row * NUM_FIELDS + j]) + j * FIELD_DIM;

    // Two independent 256-bit gathers in flight per thread.
    uint32_t a[8], b[8];
    ldg8(W + ((size_t)j * VOCAB + ii) * 32 + q * 8, a);
    ldg8(W + ((size_t)i * VOCAB + jj) * 32 + q * 8, b);

    // out float layout: (row, pair, 32); 4 lanes cover one contiguous 128B line.
    float* o = out + (size_t)row * (NUM_PAIRS * 32) + p * 32 + q * 8;
    stg_cs(o,
           __uint_as_float(a[0]) * __uint_as_float(b[0]),
           __uint_as_float(a[1]) * __uint_as_float(b[1]),
           __uint_as_float(a[2]) * __uint_as_float(b[2]),
           __uint_as_float(a[3]) * __uint_as_float(b[3]));
    stg_cs(o + 4,
           __uint_as_float(a[4]) * __uint_as_float(b[4]),
           __uint_as_float(a[5]) * __uint_as_float(b[5]),
           __uint_as_float(a[6]) * __uint_as_float(b[6]),
           __uint_as_float(a[7]) * __uint_as_float(b[7]));
}

extern "C" void kernel_launch(void* const* d_in, const int* in_sizes, int n_in,
                              void* d_out, int out_size)
{
    // Inputs: x int32 (16384*16 elems), W float32 (16*500000*32 elems).
    const int* x = nullptr;
    const float* W = nullptr;
    int x_elems = 0;
    if (n_in >= 2) {
        if (in_sizes[0] < in_sizes[1]) {
            x = (const int*)d_in[0];
            W = (const float*)d_in[1];
            x_elems = in_sizes[0];
        } else {
            x = (const int*)d_in[1];
            W = (const float*)d_in[0];
            x_elems = in_sizes[1];
        }
    }

    const int batch = x_elems / NUM_FIELDS;
    const int tiles = batch / ROWS_PER_BLOCK;   // 16384/128 = 128

    dim3 grid(tiles, NUM_PAIRS);
    ffm_pairmajor_kernel<<<grid, TPB>>>(x, W, (float*)d_out, batch);
}

// round 15
// speedup vs baseline: 1.0054x; 1.0013x over previous
#include <cuda_runtime.h>
#include <cstddef>
#include <cstdint>

#define NUM_FIELDS 16
#define FIELD_DIM  31250
#define VOCAB      500000
#define NUM_PAIRS  120
#define ROWS_PER_BLOCK 128
#define TPB 512            // 128 rows * 4 lanes (32B per lane), 1 row per thread

// Packed (i,j) pair table for triu(16, k=1): entry = i | (j<<8).
#define P(i,j) ((i) | ((j) << 8))
__constant__ int c_pair[NUM_PAIRS] = {
    P(0,1),P(0,2),P(0,3),P(0,4),P(0,5),P(0,6),P(0,7),P(0,8),P(0,9),P(0,10),P(0,11),P(0,12),P(0,13),P(0,14),P(0,15),
    P(1,2),P(1,3),P(1,4),P(1,5),P(1,6),P(1,7),P(1,8),P(1,9),P(1,10),P(1,11),P(1,12),P(1,13),P(1,14),P(1,15),
    P(2,3),P(2,4),P(2,5),P(2,6),P(2,7),P(2,8),P(2,9),P(2,10),P(2,11),P(2,12),P(2,13),P(2,14),P(2,15),
    P(3,4),P(3,5),P(3,6),P(3,7),P(3,8),P(3,9),P(3,10),P(3,11),P(3,12),P(3,13),P(3,14),P(3,15),
    P(4,5),P(4,6),P(4,7),P(4,8),P(4,9),P(4,10),P(4,11),P(4,12),P(4,13),P(4,14),P(4,15),
    P(5,6),P(5,7),P(5,8),P(5,9),P(5,10),P(5,11),P(5,12),P(5,13),P(5,14),P(5,15),
    P(6,7),P(6,8),P(6,9),P(6,10),P(6,11),P(6,12),P(6,13),P(6,14),P(6,15),
    P(7,8),P(7,9),P(7,10),P(7,11),P(7,12),P(7,13),P(7,14),P(7,15),
    P(8,9),P(8,10),P(8,11),P(8,12),P(8,13),P(8,14),P(8,15),
    P(9,10),P(9,11),P(9,12),P(9,13),P(9,14),P(9,15),
    P(10,11),P(10,12),P(10,13),P(10,14),P(10,15),
    P(11,12),P(11,13),P(11,14),P(11,15),
    P(12,13),P(12,14),P(12,15),
    P(13,14),P(13,15),
    P(14,15)
};
#undef P

// 256-bit (32B) gather via texture/nc path.
__device__ __forceinline__ void ldg8(const float* p, uint32_t v[8]) {
    asm volatile("ld.global.nc.v8.b32 {%0,%1,%2,%3,%4,%5,%6,%7}, [%8];"
                 : "=r"(v[0]), "=r"(v[1]), "=r"(v[2]), "=r"(v[3]),
                   "=r"(v[4]), "=r"(v[5]), "=r"(v[6]), "=r"(v[7])
                 : "l"(p));
}

// Streaming store, evict-first: output is never re-read.
__device__ __forceinline__ void stg_cs(float* p, float x, float y, float z, float w) {
    asm volatile("st.global.cs.v4.f32 [%0], {%1,%2,%3,%4};"
                 :: "l"(p), "f"(x), "f"(y), "f"(z), "f"(w)
                 : "memory");
}

// Pair-major schedule: blockIdx.y = pair (contiguous block-id span per pair ->
// the pair's two 4MB index windows stay L2-resident for all 16384 accesses,
// capturing the ~22% duplicate-index read reuse; each of the 240 (slab,field)
// windows belongs to exactly one pair, so this captures ALL available reuse),
// blockIdx.x = batch tile of 128 rows. Each thread: 1 row x one 32B lane; two
// independent 256-bit gathers in flight; 4 lanes cover each 128B embedding
// line fully coalesced.
// FINAL configuration: ~100.5us wall, DRAM 6.1-6.3 TB/s = device LTS ceiling
// for this 2:1 random-read/stream-write mix at the compulsory ~600MB traffic
// floor. Converged over 7 variants and 7 repeats (cache hints, MLP, CTA
// size, load width, occupancy all within +/-0.45us noise).
__global__ __launch_bounds__(TPB, 4)
void ffm_pairmajor_kernel(const int* __restrict__ x,
                          const float* __restrict__ W,    // (16, 500000, 32) float
                          float* __restrict__ out,        // (B, 120, 32) float
                          int batch)
{
    const int p   = blockIdx.y;
    const int t   = threadIdx.x;
    const int q   = t & 3;              // 32B chunk within the 128B embedding
    const int r   = t >> 2;             // 0..127
    const int row = blockIdx.x * ROWS_PER_BLOCK + r;

    const int ij = c_pair[p];
    const int i  = ij & 0xff;
    const int j  = ij >> 8;

    // Index loads (x is 1MB, L2-resident; broadcast across the 4 lanes of a row).
    const int ii = __ldg(&x[row * NUM_FIELDS + i]) + i * FIELD_DIM;
    const int jj = __ldg(&x[row * NUM_FIELDS + j]) + j * FIELD_DIM;

    // Two independent 256-bit gathers in flight per thread.
    uint32_t a[8], b[8];
    ldg8(W + ((size_t)j * VOCAB + ii) * 32 + q * 8, a);
    ldg8(W + ((size_t)i * VOCAB + jj) * 32 + q * 8, b);

    // out float layout: (row, pair, 32); 4 lanes cover one contiguous 128B line.
    float* o = out + (size_t)row * (NUM_PAIRS * 32) + p * 32 + q * 8;
    stg_cs(o,
           __uint_as_float(a[0]) * __uint_as_float(b[0]),
           __uint_as_float(a[1]) * __uint_as_float(b[1]),
           __uint_as_float(a[2]) * __uint_as_float(b[2]),
           __uint_as_float(a[3]) * __uint_as_float(b[3]));
    stg_cs(o + 4,
           __uint_as_float(a[4]) * __uint_as_float(b[4]),
           __uint_as_float(a[5]) * __uint_as_float(b[5]),
           __uint_as_float(a[6]) * __uint_as_float(b[6]),
           __uint_as_float(a[7]) * __uint_as_float(b[7]));
}

extern "C" void kernel_launch(void* const* d_in, const int* in_sizes, int n_in,
                              void* d_out, int out_size)
{
    // Inputs: x int32 (16384*16 elems), W float32 (16*500000*32 elems).
    const int* x = nullptr;
    const float* W = nullptr;
    int x_elems = 0;
    if (n_in >= 2) {
        if (in_sizes[0] < in_sizes[1]) {
            x = (const int*)d_in[0];
            W = (const float*)d_in[1];
            x_elems = in_sizes[0];
        } else {
            x = (const int*)d_in[1];
            W = (const float*)d_in[0];
            x_elems = in_sizes[1];
        }
    }

    const int batch = x_elems / NUM_FIELDS;
    const int tiles = batch / ROWS_PER_BLOCK;   // 16384/128 = 128

    dim3 grid(tiles, NUM_PAIRS);
    ffm_pairmajor_kernel<<<grid, TPB>>>(x, W, (float*)d_out, batch);
}